// round 1
// baseline (speedup 1.0000x reference)
#include <cuda_runtime.h>
#include <math.h>

// ---------------------------------------------------------------------------
// NeuralSDE (Euler-Heun / Stratonovich) persistent kernel.
// B=512 independent samples, 1024 sequential steps.
// 128 CTAs x 256 threads, 4 samples per CTA. Small weights live transposed in
// shared memory; the big diffusion output matrix cW2 (1024x128) is transposed
// once into a __device__ scratch buffer and streamed (coalesced) from L2.
// ---------------------------------------------------------------------------

#define kH     64
#define kNoise 16
#define kData  8
#define kW     128
#define kB     512
#define kT     1025
#define kSteps 1024
#define BS     4
#define NCTA   128     /* kB / BS */
#define NTHR   256
#define kCO    1024    /* kH * kNoise */

// Transposed big weights: element (k, j) of cW2t at float index k*1024 + j.
__device__ float4 g_cW2t[kW * kCO / 4];   // 512 KB
__device__ float  g_vW2t[kW * kH];        // 32 KB, element (k, h) at k*64 + h

struct Smem {
  float vW0t[65][kW];
  float vW1t[kW][kW];
  float cW0t[65][kW];
  float cW1t[kW][kW];
  float vb0[kW], vb1[kW], vb2[kH], vscl[kH];
  float cb0[kW], cb1[kW];
  float cb2[kCO];
  float cscl[kCO];
  float roWt[kH][kData];
  float rob[kData];
  float xin[BS][68];     // [t, y] padded 65 -> 68
  float h0[BS][kW];
  float h1t[kW][BS];     // transposed: row k holds the 4 samples (float4 rows)
  float ys[BS][kH];
  float g0[BS][kH];
  float f0[BS][kH];
  float dws[BS][kNoise];
};

__global__ void transpose_kernel(const float* __restrict__ cW2,
                                 const float* __restrict__ vW2) {
  int idx = blockIdx.x * blockDim.x + threadIdx.x;
  int stride = gridDim.x * blockDim.x;
  float* ct = reinterpret_cast<float*>(g_cW2t);
  for (int i = idx; i < kW * kCO; i += stride) {
    int k = i >> 10, j = i & (kCO - 1);
    ct[i] = cW2[j * kW + k];           // cW2 is (1024, 128) row-major
  }
  for (int i = idx; i < kW * kH; i += stride) {
    int k = i >> 6, h = i & (kH - 1);
    g_vW2t[i] = vW2[h * kW + k];       // vW2 is (64, 128) row-major
  }
}

__device__ __forceinline__ float lipswish(float x) {
  return 0.909f * x * (1.0f / (1.0f + expf(-x)));
}

// out(h0) = lipswish(x @ W.T + b); thread handles neuron j for samples bp, bp+2
__device__ __forceinline__ void dense_in_h0(const float (*Wt)[kW],
                                            const float* __restrict__ bias,
                                            const float* __restrict__ x, int xstride,
                                            int K, float (*h0)[kW], int tid) {
  int j = tid & (kW - 1);
  int bp = tid >> 7;
  float a0 = bias[j];
  float a1 = a0;
#pragma unroll 4
  for (int k = 0; k < K; ++k) {
    float w = Wt[k][j];
    a0 = fmaf(w, x[bp * xstride + k], a0);
    a1 = fmaf(w, x[(bp + 2) * xstride + k], a1);
  }
  h0[bp][j] = lipswish(a0);
  h0[bp + 2][j] = lipswish(a1);
}

// h1t[j][b] = lipswish(h0 @ W.T + b)   (output stored transposed)
__device__ __forceinline__ void dense_h0_h1t(const float (*Wt)[kW],
                                             const float* __restrict__ bias,
                                             const float (*h0)[kW],
                                             float (*h1t)[BS], int tid) {
  int j = tid & (kW - 1);
  int bp = tid >> 7;
  float a0 = bias[j];
  float a1 = a0;
#pragma unroll 4
  for (int k = 0; k < kW; ++k) {
    float w = Wt[k][j];
    a0 = fmaf(w, h0[bp][k], a0);
    a1 = fmaf(w, h0[bp + 2][k], a1);
  }
  h1t[j][bp] = lipswish(a0);
  h1t[j][bp + 2] = lipswish(a1);
}

// Diffusion final layer (128 -> 1024) + tanh + cscale + contraction with dw.
// Thread owns j0 = 4*tid .. 4*tid+3 (all within one h = tid>>2, n0 = j0 & 15).
// FIRST: writes g0 to smem.  !FIRST: applies the Heun update to ys.
template <bool FIRST>
__device__ __forceinline__ void diff_l2(Smem& s, int tid) {
  int j0 = tid * 4;
  float4 bias = *reinterpret_cast<const float4*>(&s.cb2[j0]);
  float4 A0 = bias, A1 = bias, A2 = bias, A3 = bias;   // per-sample accumulators
  const float4* wp = g_cW2t + tid;                      // row k at +k*256
  const float4* xp = reinterpret_cast<const float4*>(s.h1t);
#pragma unroll 8
  for (int k = 0; k < kW; ++k) {
    float4 w = __ldg(&wp[k * (kCO / 4)]);
    float4 x = xp[k];                                   // h1 of 4 samples at k
    A0.x = fmaf(w.x, x.x, A0.x); A0.y = fmaf(w.y, x.x, A0.y);
    A0.z = fmaf(w.z, x.x, A0.z); A0.w = fmaf(w.w, x.x, A0.w);
    A1.x = fmaf(w.x, x.y, A1.x); A1.y = fmaf(w.y, x.y, A1.y);
    A1.z = fmaf(w.z, x.y, A1.z); A1.w = fmaf(w.w, x.y, A1.w);
    A2.x = fmaf(w.x, x.z, A2.x); A2.y = fmaf(w.y, x.z, A2.y);
    A2.z = fmaf(w.z, x.z, A2.z); A2.w = fmaf(w.w, x.z, A2.w);
    A3.x = fmaf(w.x, x.w, A3.x); A3.y = fmaf(w.y, x.w, A3.y);
    A3.z = fmaf(w.z, x.w, A3.z); A3.w = fmaf(w.w, x.w, A3.w);
  }
  float4 cs = *reinterpret_cast<const float4*>(&s.cscl[j0]);
  int n0 = j0 & (kNoise - 1);
  float4 d0 = *reinterpret_cast<const float4*>(&s.dws[0][n0]);
  float4 d1 = *reinterpret_cast<const float4*>(&s.dws[1][n0]);
  float4 d2 = *reinterpret_cast<const float4*>(&s.dws[2][n0]);
  float4 d3 = *reinterpret_cast<const float4*>(&s.dws[3][n0]);

  float p0 = tanhf(A0.x) * cs.x * d0.x + tanhf(A0.y) * cs.y * d0.y +
             tanhf(A0.z) * cs.z * d0.z + tanhf(A0.w) * cs.w * d0.w;
  float p1 = tanhf(A1.x) * cs.x * d1.x + tanhf(A1.y) * cs.y * d1.y +
             tanhf(A1.z) * cs.z * d1.z + tanhf(A1.w) * cs.w * d1.w;
  float p2 = tanhf(A2.x) * cs.x * d2.x + tanhf(A2.y) * cs.y * d2.y +
             tanhf(A2.z) * cs.z * d2.z + tanhf(A2.w) * cs.w * d2.w;
  float p3 = tanhf(A3.x) * cs.x * d3.x + tanhf(A3.y) * cs.y * d3.y +
             tanhf(A3.z) * cs.z * d3.z + tanhf(A3.w) * cs.w * d3.w;

  // reduce over the 4 lanes holding the 16 noise channels of this h
  p0 += __shfl_xor_sync(0xffffffffu, p0, 1); p0 += __shfl_xor_sync(0xffffffffu, p0, 2);
  p1 += __shfl_xor_sync(0xffffffffu, p1, 1); p1 += __shfl_xor_sync(0xffffffffu, p1, 2);
  p2 += __shfl_xor_sync(0xffffffffu, p2, 1); p2 += __shfl_xor_sync(0xffffffffu, p2, 2);
  p3 += __shfl_xor_sync(0xffffffffu, p3, 1); p3 += __shfl_xor_sync(0xffffffffu, p3, 2);

  if ((tid & 3) == 0) {
    int h = tid >> 2;
    if (FIRST) {
      s.g0[0][h] = p0; s.g0[1][h] = p1; s.g0[2][h] = p2; s.g0[3][h] = p3;
    } else {
      s.ys[0][h] += s.f0[0][h] + 0.5f * (s.g0[0][h] + p0);
      s.ys[1][h] += s.f0[1][h] + 0.5f * (s.g0[1][h] + p1);
      s.ys[2][h] += s.f0[2][h] + 0.5f * (s.g0[2][h] + p2);
      s.ys[3][h] += s.f0[3][h] + 0.5f * (s.g0[3][h] + p3);
    }
  }
}

// Drift final layer (128 -> 64) + tanh * vscale * dt, streamed vW2t from L2.
__device__ __forceinline__ void drift_l2(Smem& s, int tid, float dt) {
  int b = tid >> 6, h = tid & (kH - 1);
  float acc = s.vb2[h];
#pragma unroll 8
  for (int k = 0; k < kW; ++k)
    acc = fmaf(s.h1t[k][b], __ldg(&g_vW2t[k * kH + h]), acc);
  s.f0[b][h] = s.vscl[h] * tanhf(acc) * dt;
}

__device__ __forceinline__ void readout(const Smem& s, float* __restrict__ out,
                                        int bbase, int tidx, int tid) {
  if (tid < BS * kData) {
    int b = tid >> 3, d = tid & 7;
    float acc = s.rob[d];
#pragma unroll
    for (int h = 0; h < kH; ++h) acc = fmaf(s.ys[b][h], s.roWt[h][d], acc);
    out[((size_t)(bbase + b) * kT + tidx) * kData + d] = acc;
  }
}

__global__ __launch_bounds__(NTHR) void sde_kernel(
    const float* __restrict__ ts, const float* __restrict__ z0,
    const float* __restrict__ dW,
    const float* __restrict__ iW0, const float* __restrict__ ib0,
    const float* __restrict__ iW1, const float* __restrict__ ib1,
    const float* __restrict__ iW2, const float* __restrict__ ib2,
    const float* __restrict__ vW0, const float* __restrict__ vb0,
    const float* __restrict__ vW1, const float* __restrict__ vb1,
    const float* __restrict__ vb2, const float* __restrict__ vscale,
    const float* __restrict__ cW0, const float* __restrict__ cb0,
    const float* __restrict__ cW1, const float* __restrict__ cb1,
    const float* __restrict__ cb2, const float* __restrict__ cscale,
    const float* __restrict__ roW, const float* __restrict__ rob,
    float* __restrict__ out) {
  extern __shared__ char smem_raw[];
  Smem& s = *reinterpret_cast<Smem*>(smem_raw);
  const int tid = threadIdx.x;
  const int bbase = blockIdx.x * BS;

  // ---- load small weights transposed into smem ----
  for (int i = tid; i < 65 * kW; i += NTHR) {
    int k = i >> 7, j = i & 127;
    s.vW0t[k][j] = vW0[j * 65 + k];
    s.cW0t[k][j] = cW0[j * 65 + k];
  }
  for (int i = tid; i < kW * kW; i += NTHR) {
    int k = i >> 7, j = i & 127;
    s.vW1t[k][j] = vW1[j * kW + k];
    s.cW1t[k][j] = cW1[j * kW + k];
  }
  for (int i = tid; i < kW; i += NTHR) {
    s.vb0[i] = vb0[i]; s.vb1[i] = vb1[i];
    s.cb0[i] = cb0[i]; s.cb1[i] = cb1[i];
  }
  for (int i = tid; i < kH; i += NTHR) { s.vb2[i] = vb2[i]; s.vscl[i] = vscale[i]; }
  for (int i = tid; i < kCO; i += NTHR) { s.cb2[i] = cb2[i]; s.cscl[i] = cscale[i]; }
  for (int i = tid; i < kH * kData; i += NTHR) {
    int h = i >> 3, d = i & 7;
    s.roWt[h][d] = roW[d * kH + h];
  }
  if (tid < kData) s.rob[tid] = rob[tid];
  __syncthreads();

  const float tszero = __ldg(&ts[0]);
  const float dt = __ldg(&ts[1]) - tszero;
  const float sqdt = sqrtf(dt);

  // ---- initial MLP: z0 (8) -> relu 128 -> relu 128 -> 64 (identity) ----
  {
    int j = tid & 127, bp = tid >> 7;
    float a0 = __ldg(&ib0[j]), a1 = a0;
#pragma unroll
    for (int k = 0; k < 8; ++k) {
      float w = __ldg(&iW0[j * 8 + k]);
      a0 = fmaf(w, __ldg(&z0[(bbase + bp) * 8 + k]), a0);
      a1 = fmaf(w, __ldg(&z0[(bbase + bp + 2) * 8 + k]), a1);
    }
    s.h0[bp][j] = fmaxf(a0, 0.f);
    s.h0[bp + 2][j] = fmaxf(a1, 0.f);
  }
  __syncthreads();
  {
    int j = tid & 127, bp = tid >> 7;
    float a0 = __ldg(&ib1[j]), a1 = a0;
#pragma unroll 4
    for (int k = 0; k < kW; ++k) {
      float w = __ldg(&iW1[j * kW + k]);
      a0 = fmaf(w, s.h0[bp][k], a0);
      a1 = fmaf(w, s.h0[bp + 2][k], a1);
    }
    s.h1t[j][bp] = fmaxf(a0, 0.f);
    s.h1t[j][bp + 2] = fmaxf(a1, 0.f);
  }
  __syncthreads();
  {
    int b = tid >> 6, h = tid & 63;
    float acc = __ldg(&ib2[h]);
#pragma unroll 4
    for (int k = 0; k < kW; ++k)
      acc = fmaf(s.h1t[k][b], __ldg(&iW2[h * kW + k]), acc);
    s.ys[b][h] = acc;
  }
  __syncthreads();
  readout(s, out, bbase, 0, tid);

  // ---- sequential Euler-Heun scan ----
  for (int st = 0; st < kSteps; ++st) {
    float tcur = __ldg(&ts[st]);
    if (tid < BS * kNoise) {
      int b = tid >> 4, n = tid & 15;
      s.dws[b][n] = __ldg(&dW[((size_t)st * kB + bbase + b) * kNoise + n]) * sqdt;
    }
    for (int i = tid; i < BS * 65; i += NTHR) {
      int b = i / 65, k = i - 65 * b;
      s.xin[b][k] = (k == 0) ? tcur : s.ys[b][k - 1];
    }
    __syncthreads();

    // drift f0 = vscale * tanh(vMLP(t, y)) * dt
    dense_in_h0(s.vW0t, s.vb0, &s.xin[0][0], 68, 65, s.h0, tid);
    __syncthreads();
    dense_h0_h1t(s.vW1t, s.vb1, s.h0, s.h1t, tid);
    __syncthreads();
    drift_l2(s, tid, dt);
    __syncthreads();

    // diffusion eval 1: g0 at y
    dense_in_h0(s.cW0t, s.cb0, &s.xin[0][0], 68, 65, s.h0, tid);
    __syncthreads();
    dense_h0_h1t(s.cW1t, s.cb1, s.h0, s.h1t, tid);
    __syncthreads();
    diff_l2<true>(s, tid);
    __syncthreads();

    // diffusion eval 2 at y' = y + g0, then Heun update of ys
    for (int i = tid; i < BS * 65; i += NTHR) {
      int b = i / 65, k = i - 65 * b;
      s.xin[b][k] = (k == 0) ? tcur : (s.ys[b][k - 1] + s.g0[b][k - 1]);
    }
    __syncthreads();
    dense_in_h0(s.cW0t, s.cb0, &s.xin[0][0], 68, 65, s.h0, tid);
    __syncthreads();
    dense_h0_h1t(s.cW1t, s.cb1, s.h0, s.h1t, tid);
    __syncthreads();
    diff_l2<false>(s, tid);
    __syncthreads();

    readout(s, out, bbase, st + 1, tid);
  }
}

extern "C" void kernel_launch(void* const* d_in, const int* in_sizes, int n_in,
                              void* d_out, int out_size) {
  (void)in_sizes; (void)n_in; (void)out_size;
  const float* ts     = (const float*)d_in[0];
  const float* z0     = (const float*)d_in[1];
  const float* dW     = (const float*)d_in[2];
  const float* iW0    = (const float*)d_in[3];
  const float* ib0    = (const float*)d_in[4];
  const float* iW1    = (const float*)d_in[5];
  const float* ib1    = (const float*)d_in[6];
  const float* iW2    = (const float*)d_in[7];
  const float* ib2    = (const float*)d_in[8];
  const float* vW0    = (const float*)d_in[9];
  const float* vb0    = (const float*)d_in[10];
  const float* vW1    = (const float*)d_in[11];
  const float* vb1    = (const float*)d_in[12];
  const float* vW2    = (const float*)d_in[13];
  const float* vb2    = (const float*)d_in[14];
  const float* vscale = (const float*)d_in[15];
  const float* cW0    = (const float*)d_in[16];
  const float* cb0    = (const float*)d_in[17];
  const float* cW1    = (const float*)d_in[18];
  const float* cb1    = (const float*)d_in[19];
  const float* cW2    = (const float*)d_in[20];
  const float* cb2    = (const float*)d_in[21];
  const float* cscale = (const float*)d_in[22];
  const float* roW    = (const float*)d_in[23];
  const float* rob    = (const float*)d_in[24];

  cudaFuncSetAttribute(sde_kernel, cudaFuncAttributeMaxDynamicSharedMemorySize,
                       (int)sizeof(Smem));

  transpose_kernel<<<132, 256>>>(cW2, vW2);
  sde_kernel<<<NCTA, NTHR, sizeof(Smem)>>>(
      ts, z0, dW, iW0, ib0, iW1, ib1, iW2, ib2,
      vW0, vb0, vW1, vb1, vb2, vscale,
      cW0, cb0, cW1, cb1, cb2, cscale, roW, rob,
      (float*)d_out);
}

// round 2
// speedup vs baseline: 1.0045x; 1.0045x over previous
#include <cuda_runtime.h>
#include <math.h>

// ---------------------------------------------------------------------------
// NeuralSDE (Euler-Heun / Stratonovich) persistent kernel.
// B=512 independent samples, 1024 sequential steps.
// 128 CTAs x 256 threads, 4 samples per CTA. Small weights live transposed in
// shared memory; the big diffusion output matrix cW2 (1024x128) is transposed
// once into a __device__ scratch buffer and streamed (coalesced) from L2.
// ---------------------------------------------------------------------------

#define kH     64
#define kNoise 16
#define kData  8
#define kW     128
#define kB     512
#define kT     1025
#define kSteps 1024
#define BS     4
#define NCTA   128     /* kB / BS */
#define NTHR   256
#define kCO    1024    /* kH * kNoise */

// Transposed big weights: element (k, j) of cW2t at float index k*1024 + j.
__device__ float4 g_cW2t[kW * kCO / 4];   // 512 KB
__device__ float  g_vW2t[kW * kH];        // 32 KB, element (k, h) at k*64 + h

struct Smem {
  float vW0t[65][kW];
  float vW1t[kW][kW];
  float cW0t[65][kW];
  float cW1t[kW][kW];
  float vb0[kW], vb1[kW], vb2[kH], vscl[kH];
  float cb0[kW], cb1[kW];
  float cb2[kCO];
  float cscl[kCO];
  float roWt[kH][kData];
  float rob[kData];
  float xin[BS][68];     // [t, y] padded 65 -> 68
  float h0[BS][kW];
  float h1t[kW][BS];     // transposed: row k holds the 4 samples (float4 rows)
  float ys[BS][kH];
  float g0[BS][kH];
  float f0[BS][kH];
  float dws[BS][kNoise];
};

__global__ void transpose_kernel(const float* __restrict__ cW2,
                                 const float* __restrict__ vW2) {
  int idx = blockIdx.x * blockDim.x + threadIdx.x;
  int stride = gridDim.x * blockDim.x;
  float* ct = reinterpret_cast<float*>(g_cW2t);
  for (int i = idx; i < kW * kCO; i += stride) {
    int k = i >> 10, j = i & (kCO - 1);
    ct[i] = cW2[j * kW + k];           // cW2 is (1024, 128) row-major
  }
  for (int i = idx; i < kW * kH; i += stride) {
    int k = i >> 6, h = i & (kH - 1);
    g_vW2t[i] = vW2[h * kW + k];       // vW2 is (64, 128) row-major
  }
}

__device__ __forceinline__ float lipswish(float x) {
  return 0.909f * x * (1.0f / (1.0f + expf(-x)));
}

// out(h0) = lipswish(x @ W.T + b); thread handles neuron j for samples bp, bp+2
__device__ __forceinline__ void dense_in_h0(const float (*Wt)[kW],
                                            const float* __restrict__ bias,
                                            const float* __restrict__ x, int xstride,
                                            int K, float (*h0)[kW], int tid) {
  int j = tid & (kW - 1);
  int bp = tid >> 7;
  float a0 = bias[j];
  float a1 = a0;
#pragma unroll 4
  for (int k = 0; k < K; ++k) {
    float w = Wt[k][j];
    a0 = fmaf(w, x[bp * xstride + k], a0);
    a1 = fmaf(w, x[(bp + 2) * xstride + k], a1);
  }
  h0[bp][j] = lipswish(a0);
  h0[bp + 2][j] = lipswish(a1);
}

// h1t[j][b] = lipswish(h0 @ W.T + b)   (output stored transposed)
__device__ __forceinline__ void dense_h0_h1t(const float (*Wt)[kW],
                                             const float* __restrict__ bias,
                                             const float (*h0)[kW],
                                             float (*h1t)[BS], int tid) {
  int j = tid & (kW - 1);
  int bp = tid >> 7;
  float a0 = bias[j];
  float a1 = a0;
#pragma unroll 4
  for (int k = 0; k < kW; ++k) {
    float w = Wt[k][j];
    a0 = fmaf(w, h0[bp][k], a0);
    a1 = fmaf(w, h0[bp + 2][k], a1);
  }
  h1t[j][bp] = lipswish(a0);
  h1t[j][bp + 2] = lipswish(a1);
}

// Diffusion final layer (128 -> 1024) + tanh + cscale + contraction with dw.
// Thread owns j0 = 4*tid .. 4*tid+3 (all within one h = tid>>2, n0 = j0 & 15).
// FIRST: writes g0 to smem.  !FIRST: applies the Heun update to ys.
template <bool FIRST>
__device__ __forceinline__ void diff_l2(Smem& s, int tid) {
  int j0 = tid * 4;
  float4 bias = *reinterpret_cast<const float4*>(&s.cb2[j0]);
  float4 A0 = bias, A1 = bias, A2 = bias, A3 = bias;   // per-sample accumulators
  const float4* wp = g_cW2t + tid;                      // row k at +k*256
  const float4* xp = reinterpret_cast<const float4*>(s.h1t);
#pragma unroll 8
  for (int k = 0; k < kW; ++k) {
    float4 w = __ldg(&wp[k * (kCO / 4)]);
    float4 x = xp[k];                                   // h1 of 4 samples at k
    A0.x = fmaf(w.x, x.x, A0.x); A0.y = fmaf(w.y, x.x, A0.y);
    A0.z = fmaf(w.z, x.x, A0.z); A0.w = fmaf(w.w, x.x, A0.w);
    A1.x = fmaf(w.x, x.y, A1.x); A1.y = fmaf(w.y, x.y, A1.y);
    A1.z = fmaf(w.z, x.y, A1.z); A1.w = fmaf(w.w, x.y, A1.w);
    A2.x = fmaf(w.x, x.z, A2.x); A2.y = fmaf(w.y, x.z, A2.y);
    A2.z = fmaf(w.z, x.z, A2.z); A2.w = fmaf(w.w, x.z, A2.w);
    A3.x = fmaf(w.x, x.w, A3.x); A3.y = fmaf(w.y, x.w, A3.y);
    A3.z = fmaf(w.z, x.w, A3.z); A3.w = fmaf(w.w, x.w, A3.w);
  }
  float4 cs = *reinterpret_cast<const float4*>(&s.cscl[j0]);
  int n0 = j0 & (kNoise - 1);
  float4 d0 = *reinterpret_cast<const float4*>(&s.dws[0][n0]);
  float4 d1 = *reinterpret_cast<const float4*>(&s.dws[1][n0]);
  float4 d2 = *reinterpret_cast<const float4*>(&s.dws[2][n0]);
  float4 d3 = *reinterpret_cast<const float4*>(&s.dws[3][n0]);

  float p0 = tanhf(A0.x) * cs.x * d0.x + tanhf(A0.y) * cs.y * d0.y +
             tanhf(A0.z) * cs.z * d0.z + tanhf(A0.w) * cs.w * d0.w;
  float p1 = tanhf(A1.x) * cs.x * d1.x + tanhf(A1.y) * cs.y * d1.y +
             tanhf(A1.z) * cs.z * d1.z + tanhf(A1.w) * cs.w * d1.w;
  float p2 = tanhf(A2.x) * cs.x * d2.x + tanhf(A2.y) * cs.y * d2.y +
             tanhf(A2.z) * cs.z * d2.z + tanhf(A2.w) * cs.w * d2.w;
  float p3 = tanhf(A3.x) * cs.x * d3.x + tanhf(A3.y) * cs.y * d3.y +
             tanhf(A3.z) * cs.z * d3.z + tanhf(A3.w) * cs.w * d3.w;

  // reduce over the 4 lanes holding the 16 noise channels of this h
  p0 += __shfl_xor_sync(0xffffffffu, p0, 1); p0 += __shfl_xor_sync(0xffffffffu, p0, 2);
  p1 += __shfl_xor_sync(0xffffffffu, p1, 1); p1 += __shfl_xor_sync(0xffffffffu, p1, 2);
  p2 += __shfl_xor_sync(0xffffffffu, p2, 1); p2 += __shfl_xor_sync(0xffffffffu, p2, 2);
  p3 += __shfl_xor_sync(0xffffffffu, p3, 1); p3 += __shfl_xor_sync(0xffffffffu, p3, 2);

  if ((tid & 3) == 0) {
    int h = tid >> 2;
    if (FIRST) {
      s.g0[0][h] = p0; s.g0[1][h] = p1; s.g0[2][h] = p2; s.g0[3][h] = p3;
    } else {
      s.ys[0][h] += s.f0[0][h] + 0.5f * (s.g0[0][h] + p0);
      s.ys[1][h] += s.f0[1][h] + 0.5f * (s.g0[1][h] + p1);
      s.ys[2][h] += s.f0[2][h] + 0.5f * (s.g0[2][h] + p2);
      s.ys[3][h] += s.f0[3][h] + 0.5f * (s.g0[3][h] + p3);
    }
  }
}

// Drift final layer (128 -> 64) + tanh * vscale * dt, streamed vW2t from L2.
__device__ __forceinline__ void drift_l2(Smem& s, int tid, float dt) {
  int b = tid >> 6, h = tid & (kH - 1);
  float acc = s.vb2[h];
#pragma unroll 8
  for (int k = 0; k < kW; ++k)
    acc = fmaf(s.h1t[k][b], __ldg(&g_vW2t[k * kH + h]), acc);
  s.f0[b][h] = s.vscl[h] * tanhf(acc) * dt;
}

__device__ __forceinline__ void readout(const Smem& s, float* __restrict__ out,
                                        int bbase, int tidx, int tid) {
  if (tid < BS * kData) {
    int b = tid >> 3, d = tid & 7;
    float acc = s.rob[d];
#pragma unroll
    for (int h = 0; h < kH; ++h) acc = fmaf(s.ys[b][h], s.roWt[h][d], acc);
    out[((size_t)(bbase + b) * kT + tidx) * kData + d] = acc;
  }
}

__global__ __launch_bounds__(NTHR) void sde_kernel(
    const float* __restrict__ ts, const float* __restrict__ z0,
    const float* __restrict__ dW,
    const float* __restrict__ iW0, const float* __restrict__ ib0,
    const float* __restrict__ iW1, const float* __restrict__ ib1,
    const float* __restrict__ iW2, const float* __restrict__ ib2,
    const float* __restrict__ vW0, const float* __restrict__ vb0,
    const float* __restrict__ vW1, const float* __restrict__ vb1,
    const float* __restrict__ vb2, const float* __restrict__ vscale,
    const float* __restrict__ cW0, const float* __restrict__ cb0,
    const float* __restrict__ cW1, const float* __restrict__ cb1,
    const float* __restrict__ cb2, const float* __restrict__ cscale,
    const float* __restrict__ roW, const float* __restrict__ rob,
    float* __restrict__ out) {
  extern __shared__ char smem_raw[];
  Smem& s = *reinterpret_cast<Smem*>(smem_raw);
  const int tid = threadIdx.x;
  const int bbase = blockIdx.x * BS;

  // ---- load small weights transposed into smem ----
  for (int i = tid; i < 65 * kW; i += NTHR) {
    int k = i >> 7, j = i & 127;
    s.vW0t[k][j] = vW0[j * 65 + k];
    s.cW0t[k][j] = cW0[j * 65 + k];
  }
  for (int i = tid; i < kW * kW; i += NTHR) {
    int k = i >> 7, j = i & 127;
    s.vW1t[k][j] = vW1[j * kW + k];
    s.cW1t[k][j] = cW1[j * kW + k];
  }
  for (int i = tid; i < kW; i += NTHR) {
    s.vb0[i] = vb0[i]; s.vb1[i] = vb1[i];
    s.cb0[i] = cb0[i]; s.cb1[i] = cb1[i];
  }
  for (int i = tid; i < kH; i += NTHR) { s.vb2[i] = vb2[i]; s.vscl[i] = vscale[i]; }
  for (int i = tid; i < kCO; i += NTHR) { s.cb2[i] = cb2[i]; s.cscl[i] = cscale[i]; }
  for (int i = tid; i < kH * kData; i += NTHR) {
    int h = i >> 3, d = i & 7;
    s.roWt[h][d] = roW[d * kH + h];
  }
  if (tid < kData) s.rob[tid] = rob[tid];
  __syncthreads();

  const float tszero = __ldg(&ts[0]);
  const float dt = __ldg(&ts[1]) - tszero;
  const float sqdt = sqrtf(dt);

  // ---- initial MLP: z0 (8) -> relu 128 -> relu 128 -> 64 (identity) ----
  {
    int j = tid & 127, bp = tid >> 7;
    float a0 = __ldg(&ib0[j]), a1 = a0;
#pragma unroll
    for (int k = 0; k < 8; ++k) {
      float w = __ldg(&iW0[j * 8 + k]);
      a0 = fmaf(w, __ldg(&z0[(bbase + bp) * 8 + k]), a0);
      a1 = fmaf(w, __ldg(&z0[(bbase + bp + 2) * 8 + k]), a1);
    }
    s.h0[bp][j] = fmaxf(a0, 0.f);
    s.h0[bp + 2][j] = fmaxf(a1, 0.f);
  }
  __syncthreads();
  {
    int j = tid & 127, bp = tid >> 7;
    float a0 = __ldg(&ib1[j]), a1 = a0;
#pragma unroll 4
    for (int k = 0; k < kW; ++k) {
      float w = __ldg(&iW1[j * kW + k]);
      a0 = fmaf(w, s.h0[bp][k], a0);
      a1 = fmaf(w, s.h0[bp + 2][k], a1);
    }
    s.h1t[j][bp] = fmaxf(a0, 0.f);
    s.h1t[j][bp + 2] = fmaxf(a1, 0.f);
  }
  __syncthreads();
  {
    int b = tid >> 6, h = tid & 63;
    float acc = __ldg(&ib2[h]);
#pragma unroll 4
    for (int k = 0; k < kW; ++k)
      acc = fmaf(s.h1t[k][b], __ldg(&iW2[h * kW + k]), acc);
    s.ys[b][h] = acc;
  }
  __syncthreads();
  readout(s, out, bbase, 0, tid);

  // ---- sequential Euler-Heun scan ----
  for (int st = 0; st < kSteps; ++st) {
    float tcur = __ldg(&ts[st]);
    if (tid < BS * kNoise) {
      int b = tid >> 4, n = tid & 15;
      s.dws[b][n] = __ldg(&dW[((size_t)st * kB + bbase + b) * kNoise + n]) * sqdt;
    }
    for (int i = tid; i < BS * 65; i += NTHR) {
      int b = i / 65, k = i - 65 * b;
      s.xin[b][k] = (k == 0) ? tcur : s.ys[b][k - 1];
    }
    __syncthreads();

    // drift f0 = vscale * tanh(vMLP(t, y)) * dt
    dense_in_h0(s.vW0t, s.vb0, &s.xin[0][0], 68, 65, s.h0, tid);
    __syncthreads();
    dense_h0_h1t(s.vW1t, s.vb1, s.h0, s.h1t, tid);
    __syncthreads();
    drift_l2(s, tid, dt);
    __syncthreads();

    // diffusion eval 1: g0 at y
    dense_in_h0(s.cW0t, s.cb0, &s.xin[0][0], 68, 65, s.h0, tid);
    __syncthreads();
    dense_h0_h1t(s.cW1t, s.cb1, s.h0, s.h1t, tid);
    __syncthreads();
    diff_l2<true>(s, tid);
    __syncthreads();

    // diffusion eval 2 at y' = y + g0, then Heun update of ys
    for (int i = tid; i < BS * 65; i += NTHR) {
      int b = i / 65, k = i - 65 * b;
      s.xin[b][k] = (k == 0) ? tcur : (s.ys[b][k - 1] + s.g0[b][k - 1]);
    }
    __syncthreads();
    dense_in_h0(s.cW0t, s.cb0, &s.xin[0][0], 68, 65, s.h0, tid);
    __syncthreads();
    dense_h0_h1t(s.cW1t, s.cb1, s.h0, s.h1t, tid);
    __syncthreads();
    diff_l2<false>(s, tid);
    __syncthreads();

    readout(s, out, bbase, st + 1, tid);
  }
}

extern "C" void kernel_launch(void* const* d_in, const int* in_sizes, int n_in,
                              void* d_out, int out_size) {
  (void)in_sizes; (void)n_in; (void)out_size;
  const float* ts     = (const float*)d_in[0];
  const float* z0     = (const float*)d_in[1];
  const float* dW     = (const float*)d_in[2];
  const float* iW0    = (const float*)d_in[3];
  const float* ib0    = (const float*)d_in[4];
  const float* iW1    = (const float*)d_in[5];
  const float* ib1    = (const float*)d_in[6];
  const float* iW2    = (const float*)d_in[7];
  const float* ib2    = (const float*)d_in[8];
  const float* vW0    = (const float*)d_in[9];
  const float* vb0    = (const float*)d_in[10];
  const float* vW1    = (const float*)d_in[11];
  const float* vb1    = (const float*)d_in[12];
  const float* vW2    = (const float*)d_in[13];
  const float* vb2    = (const float*)d_in[14];
  const float* vscale = (const float*)d_in[15];
  const float* cW0    = (const float*)d_in[16];
  const float* cb0    = (const float*)d_in[17];
  const float* cW1    = (const float*)d_in[18];
  const float* cb1    = (const float*)d_in[19];
  const float* cW2    = (const float*)d_in[20];
  const float* cb2    = (const float*)d_in[21];
  const float* cscale = (const float*)d_in[22];
  const float* roW    = (const float*)d_in[23];
  const float* rob    = (const float*)d_in[24];

  cudaFuncSetAttribute(sde_kernel, cudaFuncAttributeMaxDynamicSharedMemorySize,
                       (int)sizeof(Smem));

  transpose_kernel<<<132, 256>>>(cW2, vW2);
  sde_kernel<<<NCTA, NTHR, sizeof(Smem)>>>(
      ts, z0, dW, iW0, ib0, iW1, ib1, iW2, ib2,
      vW0, vb0, vW1, vb1, vb2, vscale,
      cW0, cb0, cW1, cb1, cb2, cscale, roW, rob,
      (float*)d_out);
}

// round 3
// speedup vs baseline: 1.7739x; 1.7659x over previous
#include <cuda_runtime.h>
#include <math.h>

// ---------------------------------------------------------------------------
// NeuralSDE (Euler-Heun / Stratonovich) persistent kernel, round 2.
// 128 CTAs x 512 threads, 4 samples per CTA. 6 barriers/step, packed f32x2
// FMA in all dense loops, drift folded into the diffusion phase, readout and
// dW loads folded into phase A.
// ---------------------------------------------------------------------------

#define kH     64
#define kNoise 16
#define kData  8
#define kW     128
#define kB     512
#define kT     1025
#define kSteps 1024
#define BS     4
#define NCTA   128
#define NTHR   512
#define kCO    1024

using u64 = unsigned long long;

// Transposed big weights (k-major). 8B-aligned for packed loads.
__device__ u64   g_cW2t[kW * kCO / 2];   // float (k,j) at k*1024 + j
__device__ float g_vW2t[kW * kH];        // float (k,h) at k*64 + h

struct Smem {
  float vW0t[65][kW];
  float cW0t[65][kW];
  float vW1t[kW][kW];
  float cW1t[kW][kW];
  float vb0[kW], vb1[kW], cb0[kW], cb1[kW];
  float vb2[kH], vscl[kH];
  float cb2[kCO];
  float cscl[kCO];
  float roWt[kH][kData];
  float rob[kData];
  // activations: float4 over the 4 samples
  float4 ys4[kH];
  float4 g04[kH];
  float4 f04[kH];
  float4 yp4[kH];
  float4 h0v4[kW];
  float4 h0c4[kW];
  float4 h1v4[kW];
  float4 h1c4[kW];
  float  dws[BS][kNoise];
};

__global__ void transpose_kernel(const float* __restrict__ cW2,
                                 const float* __restrict__ vW2) {
  int idx = blockIdx.x * blockDim.x + threadIdx.x;
  int stride = gridDim.x * blockDim.x;
  float* ct = reinterpret_cast<float*>(g_cW2t);
  for (int i = idx; i < kW * kCO; i += stride) {
    int k = i >> 10, j = i & (kCO - 1);
    ct[i] = cW2[j * kW + k];            // cW2 is (1024, 128) row-major
  }
  for (int i = idx; i < kW * kH; i += stride) {
    int k = i >> 6, h = i & (kH - 1);
    g_vW2t[i] = vW2[h * kW + k];        // vW2 is (64, 128) row-major
  }
}

__device__ __forceinline__ u64 pack2(float lo, float hi) {
  u64 r; asm("mov.b64 %0,{%1,%2};" : "=l"(r) : "f"(lo), "f"(hi)); return r;
}
__device__ __forceinline__ void unpack2(u64 v, float& lo, float& hi) {
  asm("mov.b64 {%0,%1},%2;" : "=f"(lo), "=f"(hi) : "l"(v));
}
__device__ __forceinline__ u64 fma2(u64 a, u64 b, u64 c) {
  u64 d; asm("fma.rn.f32x2 %0,%1,%2,%3;" : "=l"(d) : "l"(a), "l"(b), "l"(c));
  return d;
}

__device__ __forceinline__ float lipswish(float x) {
  return 0.909f * x * (1.0f / (1.0f + expf(-x)));
}

__global__ __launch_bounds__(NTHR, 1) void sde_kernel(
    const float* __restrict__ ts, const float* __restrict__ z0,
    const float* __restrict__ dW,
    const float* __restrict__ iW0, const float* __restrict__ ib0,
    const float* __restrict__ iW1, const float* __restrict__ ib1,
    const float* __restrict__ iW2, const float* __restrict__ ib2,
    const float* __restrict__ vW0, const float* __restrict__ vb0,
    const float* __restrict__ vW1, const float* __restrict__ vb1,
    const float* __restrict__ vb2, const float* __restrict__ vscale,
    const float* __restrict__ cW0, const float* __restrict__ cb0,
    const float* __restrict__ cW1, const float* __restrict__ cb1,
    const float* __restrict__ cb2, const float* __restrict__ cscale,
    const float* __restrict__ roW, const float* __restrict__ rob,
    float* __restrict__ out) {
  extern __shared__ char smem_raw[];
  Smem& s = *reinterpret_cast<Smem*>(smem_raw);
  const int tid = threadIdx.x;
  const int bbase = blockIdx.x * BS;

  // ---- load small weights transposed into smem ----
  for (int i = tid; i < 65 * kW; i += NTHR) {
    int k = i >> 7, j = i & 127;
    s.vW0t[k][j] = vW0[j * 65 + k];
    s.cW0t[k][j] = cW0[j * 65 + k];
  }
  for (int i = tid; i < kW * kW; i += NTHR) {
    int k = i >> 7, j = i & 127;
    s.vW1t[k][j] = vW1[j * kW + k];
    s.cW1t[k][j] = cW1[j * kW + k];
  }
  for (int i = tid; i < kW; i += NTHR) {
    s.vb0[i] = vb0[i]; s.vb1[i] = vb1[i];
    s.cb0[i] = cb0[i]; s.cb1[i] = cb1[i];
  }
  for (int i = tid; i < kH; i += NTHR) { s.vb2[i] = vb2[i]; s.vscl[i] = vscale[i]; }
  for (int i = tid; i < kCO; i += NTHR) { s.cb2[i] = cb2[i]; s.cscl[i] = cscale[i]; }
  for (int i = tid; i < kH * kData; i += NTHR) {
    int h = i >> 3, d = i & 7;
    s.roWt[h][d] = roW[d * kH + h];
  }
  if (tid < kData) s.rob[tid] = rob[tid];
  __syncthreads();

  const float dt = __ldg(&ts[1]) - __ldg(&ts[0]);
  const float sqdt = sqrtf(dt);

  // ---- initial MLP: z0 (8) -> relu 128 -> relu 128 -> 64 ----
  if (tid < 256) {
    int j = tid & 127, pr = tid >> 7;  // samples 2pr, 2pr+1
    float a0 = __ldg(&ib0[j]), a1 = a0;
#pragma unroll
    for (int k = 0; k < 8; ++k) {
      float w = __ldg(&iW0[j * 8 + k]);
      a0 = fmaf(w, __ldg(&z0[(bbase + 2 * pr) * 8 + k]), a0);
      a1 = fmaf(w, __ldg(&z0[(bbase + 2 * pr + 1) * 8 + k]), a1);
    }
    float* d0 = reinterpret_cast<float*>(&s.h0v4[j]) + 2 * pr;
    d0[0] = fmaxf(a0, 0.f); d0[1] = fmaxf(a1, 0.f);
  }
  __syncthreads();
  if (tid < 256) {
    int j = tid & 127, pr = tid >> 7;
    float a0 = __ldg(&ib1[j]), a1 = a0;
#pragma unroll 4
    for (int k = 0; k < kW; ++k) {
      float w = __ldg(&iW1[j * kW + k]);
      const float* x = reinterpret_cast<const float*>(&s.h0v4[k]) + 2 * pr;
      a0 = fmaf(w, x[0], a0);
      a1 = fmaf(w, x[1], a1);
    }
    float* d0 = reinterpret_cast<float*>(&s.h0c4[j]) + 2 * pr;  // temp
    d0[0] = fmaxf(a0, 0.f); d0[1] = fmaxf(a1, 0.f);
  }
  __syncthreads();
  if (tid < 256) {
    int b = tid >> 6, h = tid & 63;
    float acc = __ldg(&ib2[h]);
#pragma unroll 4
    for (int k = 0; k < kW; ++k)
      acc = fmaf(reinterpret_cast<const float*>(&s.h0c4[k])[b],
                 __ldg(&iW2[h * kW + k]), acc);
    reinterpret_cast<float*>(&s.ys4[h])[b] = acc;
  }
  __syncthreads();

  // precomputed per-thread constants
  const int netc = tid >> 8;            // 0 = v, 1 = c (phases A/B)
  const int jA = tid & 127;
  const int prA = (tid >> 7) & 1;       // sample pair (0: b0,b1; 1: b2,b3)
  const int jD = (tid >> 1) & 127;      // phases D/E
  const int khD = tid & 1;
  const int prD = tid >> 8;
  const int j0 = tid << 1;              // diffusion col pair
  const int hC = tid >> 3;              // diffusion h
  const u64* wrowC = g_cW2t + tid;      // row k at + k*512 (u64 units)

  for (int st = 0; st < kSteps; ++st) {
    const float tcur = __ldg(&ts[st]);

    // ================= phase A =================
    // extras first (latency overlap): dW load + readout of current ys (index st)
    if (tid >= 448) {
      int i = tid - 448;                 // 64 tasks
      int b = i >> 4, n = i & 15;
      s.dws[b][n] = __ldg(&dW[((size_t)st * kB + bbase + b) * kNoise + n]) * sqdt;
    } else if (tid >= 416) {
      int i = tid - 416;                 // 32 tasks
      int b = i >> 3, d = i & 7;
      float acc = s.rob[d];
#pragma unroll
      for (int h = 0; h < kH; ++h)
        acc = fmaf(reinterpret_cast<const float*>(&s.ys4[h])[b], s.roWt[h][d], acc);
      out[((size_t)(bbase + b) * kT + st) * kData + d] = acc;
    }
    // dense layer 0 of BOTH nets: x = (t, ys)
    {
      const float (*W0)[kW] = netc ? s.cW0t : s.vW0t;
      const float* bb = netc ? s.cb0 : s.vb0;
      float binit = fmaf(W0[0][jA], tcur, bb[jA]);
      u64 acc = pack2(binit, binit);
#pragma unroll 8
      for (int k = 1; k <= kH; ++k) {
        float w = W0[k][jA];
        u64 x2 = *reinterpret_cast<const u64*>(
            reinterpret_cast<const float*>(&s.ys4[k - 1]) + 2 * prA);
        acc = fma2(pack2(w, w), x2, acc);
      }
      float a0, a1; unpack2(acc, a0, a1);
      float* dst = reinterpret_cast<float*>(netc ? &s.h0c4[jA] : &s.h0v4[jA]) + 2 * prA;
      float2 r; r.x = lipswish(a0); r.y = lipswish(a1);
      *reinterpret_cast<float2*>(dst) = r;
    }
    __syncthreads();

    // ================= phase B: dense layer 1 of both nets =================
    {
      const float (*W1)[kW] = netc ? s.cW1t : s.vW1t;
      const float* bb = netc ? s.cb1 : s.vb1;
      const float4* src = netc ? s.h0c4 : s.h0v4;
      float binit = bb[jA];
      u64 acc = pack2(binit, binit);
#pragma unroll 8
      for (int k = 0; k < kW; ++k) {
        float w = W1[k][jA];
        u64 x2 = *reinterpret_cast<const u64*>(
            reinterpret_cast<const float*>(&src[k]) + 2 * prA);
        acc = fma2(pack2(w, w), x2, acc);
      }
      float a0, a1; unpack2(acc, a0, a1);
      float* dst = reinterpret_cast<float*>(netc ? &s.h1c4[jA] : &s.h1v4[jA]) + 2 * prA;
      float2 r; r.x = lipswish(a0); r.y = lipswish(a1);
      *reinterpret_cast<float2*>(dst) = r;
    }
    __syncthreads();

    // ================= phase C: diffusion eval 1 + drift =================
    {
      u64 bias2 = *reinterpret_cast<const u64*>(&s.cb2[j0]);
      u64 A0 = bias2, A1 = bias2, A2 = bias2, A3 = bias2;
#pragma unroll 4
      for (int k = 0; k < kW; ++k) {
        u64 w2 = wrowC[(size_t)k * (kCO / 2)];
        float4 x = s.h1c4[k];
        A0 = fma2(w2, pack2(x.x, x.x), A0);
        A1 = fma2(w2, pack2(x.y, x.y), A1);
        A2 = fma2(w2, pack2(x.z, x.z), A2);
        A3 = fma2(w2, pack2(x.w, x.w), A3);
      }
      float csx = s.cscl[j0], csy = s.cscl[j0 + 1];
      int n0 = j0 & (kNoise - 1);
      float2 d0 = *reinterpret_cast<const float2*>(&s.dws[0][n0]);
      float2 d1 = *reinterpret_cast<const float2*>(&s.dws[1][n0]);
      float2 d2 = *reinterpret_cast<const float2*>(&s.dws[2][n0]);
      float2 d3 = *reinterpret_cast<const float2*>(&s.dws[3][n0]);
      float lo, hi;
      unpack2(A0, lo, hi); float p0 = tanhf(lo) * csx * d0.x + tanhf(hi) * csy * d0.y;
      unpack2(A1, lo, hi); float p1 = tanhf(lo) * csx * d1.x + tanhf(hi) * csy * d1.y;
      unpack2(A2, lo, hi); float p2 = tanhf(lo) * csx * d2.x + tanhf(hi) * csy * d2.y;
      unpack2(A3, lo, hi); float p3 = tanhf(lo) * csx * d3.x + tanhf(hi) * csy * d3.y;
      p0 += __shfl_xor_sync(~0u, p0, 1); p0 += __shfl_xor_sync(~0u, p0, 2); p0 += __shfl_xor_sync(~0u, p0, 4);
      p1 += __shfl_xor_sync(~0u, p1, 1); p1 += __shfl_xor_sync(~0u, p1, 2); p1 += __shfl_xor_sync(~0u, p1, 4);
      p2 += __shfl_xor_sync(~0u, p2, 1); p2 += __shfl_xor_sync(~0u, p2, 2); p2 += __shfl_xor_sync(~0u, p2, 4);
      p3 += __shfl_xor_sync(~0u, p3, 1); p3 += __shfl_xor_sync(~0u, p3, 2); p3 += __shfl_xor_sync(~0u, p3, 4);
      if ((tid & 7) == 0) {
        float4 y = s.ys4[hC];
        float4 g; g.x = p0; g.y = p1; g.z = p2; g.w = p3;
        s.g04[hC] = g;
        float4 yp; yp.x = y.x + p0; yp.y = y.y + p1; yp.z = y.z + p2; yp.w = y.w + p3;
        s.yp4[hC] = yp;
      }
    }
    if (tid < 256) {  // drift final layer (64x4 outputs)
      int b = tid >> 6, h = tid & 63;
      float acc = s.vb2[h];
#pragma unroll 8
      for (int k = 0; k < kW; ++k)
        acc = fmaf(reinterpret_cast<const float*>(&s.h1v4[k])[b],
                   __ldg(&g_vW2t[k * kH + h]), acc);
      reinterpret_cast<float*>(&s.f04[h])[b] = s.vscl[h] * tanhf(acc) * dt;
    }
    __syncthreads();

    // ================= phase D: c-net layer 0 at y' (k-split halves) ======
    {
      float binit = (khD == 0) ? fmaf(s.cW0t[0][jD], tcur, s.cb0[jD]) : 0.f;
      u64 acc = pack2(binit, binit);
      int k0 = 1 + khD * 32;
#pragma unroll 8
      for (int k = k0; k < k0 + 32; ++k) {
        float w = s.cW0t[k][jD];
        u64 x2 = *reinterpret_cast<const u64*>(
            reinterpret_cast<const float*>(&s.yp4[k - 1]) + 2 * prD);
        acc = fma2(pack2(w, w), x2, acc);
      }
      float a0, a1; unpack2(acc, a0, a1);
      a0 += __shfl_xor_sync(~0u, a0, 1);
      a1 += __shfl_xor_sync(~0u, a1, 1);
      if (khD == 0) {
        float2 r; r.x = lipswish(a0); r.y = lipswish(a1);
        *reinterpret_cast<float2*>(
            reinterpret_cast<float*>(&s.h0c4[jD]) + 2 * prD) = r;
      }
    }
    __syncthreads();

    // ================= phase E: c-net layer 1 at y' =================
    {
      float binit = (khD == 0) ? s.cb1[jD] : 0.f;
      u64 acc = pack2(binit, binit);
      int k0 = khD * 64;
#pragma unroll 8
      for (int k = k0; k < k0 + 64; ++k) {
        float w = s.cW1t[k][jD];
        u64 x2 = *reinterpret_cast<const u64*>(
            reinterpret_cast<const float*>(&s.h0c4[k]) + 2 * prD);
        acc = fma2(pack2(w, w), x2, acc);
      }
      float a0, a1; unpack2(acc, a0, a1);
      a0 += __shfl_xor_sync(~0u, a0, 1);
      a1 += __shfl_xor_sync(~0u, a1, 1);
      if (khD == 0) {
        float2 r; r.x = lipswish(a0); r.y = lipswish(a1);
        *reinterpret_cast<float2*>(
            reinterpret_cast<float*>(&s.h1c4[jD]) + 2 * prD) = r;
      }
    }
    __syncthreads();

    // ================= phase F: diffusion eval 2 + Heun update ===========
    {
      u64 bias2 = *reinterpret_cast<const u64*>(&s.cb2[j0]);
      u64 A0 = bias2, A1 = bias2, A2 = bias2, A3 = bias2;
#pragma unroll 4
      for (int k = 0; k < kW; ++k) {
        u64 w2 = wrowC[(size_t)k * (kCO / 2)];
        float4 x = s.h1c4[k];
        A0 = fma2(w2, pack2(x.x, x.x), A0);
        A1 = fma2(w2, pack2(x.y, x.y), A1);
        A2 = fma2(w2, pack2(x.z, x.z), A2);
        A3 = fma2(w2, pack2(x.w, x.w), A3);
      }
      float csx = s.cscl[j0], csy = s.cscl[j0 + 1];
      int n0 = j0 & (kNoise - 1);
      float2 d0 = *reinterpret_cast<const float2*>(&s.dws[0][n0]);
      float2 d1 = *reinterpret_cast<const float2*>(&s.dws[1][n0]);
      float2 d2 = *reinterpret_cast<const float2*>(&s.dws[2][n0]);
      float2 d3 = *reinterpret_cast<const float2*>(&s.dws[3][n0]);
      float lo, hi;
      unpack2(A0, lo, hi); float p0 = tanhf(lo) * csx * d0.x + tanhf(hi) * csy * d0.y;
      unpack2(A1, lo, hi); float p1 = tanhf(lo) * csx * d1.x + tanhf(hi) * csy * d1.y;
      unpack2(A2, lo, hi); float p2 = tanhf(lo) * csx * d2.x + tanhf(hi) * csy * d2.y;
      unpack2(A3, lo, hi); float p3 = tanhf(lo) * csx * d3.x + tanhf(hi) * csy * d3.y;
      p0 += __shfl_xor_sync(~0u, p0, 1); p0 += __shfl_xor_sync(~0u, p0, 2); p0 += __shfl_xor_sync(~0u, p0, 4);
      p1 += __shfl_xor_sync(~0u, p1, 1); p1 += __shfl_xor_sync(~0u, p1, 2); p1 += __shfl_xor_sync(~0u, p1, 4);
      p2 += __shfl_xor_sync(~0u, p2, 1); p2 += __shfl_xor_sync(~0u, p2, 2); p2 += __shfl_xor_sync(~0u, p2, 4);
      p3 += __shfl_xor_sync(~0u, p3, 1); p3 += __shfl_xor_sync(~0u, p3, 2); p3 += __shfl_xor_sync(~0u, p3, 4);
      if ((tid & 7) == 0) {
        float4 y = s.ys4[hC];
        float4 f = s.f04[hC];
        float4 g = s.g04[hC];
        y.x += f.x + 0.5f * (g.x + p0);
        y.y += f.y + 0.5f * (g.y + p1);
        y.z += f.z + 0.5f * (g.z + p2);
        y.w += f.w + 0.5f * (g.w + p3);
        s.ys4[hC] = y;
      }
    }
    __syncthreads();
  }

  // final readout (index kSteps)
  if (tid < 32) {
    int b = tid >> 3, d = tid & 7;
    float acc = s.rob[d];
#pragma unroll
    for (int h = 0; h < kH; ++h)
      acc = fmaf(reinterpret_cast<const float*>(&s.ys4[h])[b], s.roWt[h][d], acc);
    out[((size_t)(bbase + b) * kT + kSteps) * kData + d] = acc;
  }
}

extern "C" void kernel_launch(void* const* d_in, const int* in_sizes, int n_in,
                              void* d_out, int out_size) {
  (void)in_sizes; (void)n_in; (void)out_size;
  const float* ts     = (const float*)d_in[0];
  const float* z0     = (const float*)d_in[1];
  const float* dW     = (const float*)d_in[2];
  const float* iW0    = (const float*)d_in[3];
  const float* ib0    = (const float*)d_in[4];
  const float* iW1    = (const float*)d_in[5];
  const float* ib1    = (const float*)d_in[6];
  const float* iW2    = (const float*)d_in[7];
  const float* ib2    = (const float*)d_in[8];
  const float* vW0    = (const float*)d_in[9];
  const float* vb0    = (const float*)d_in[10];
  const float* vW1    = (const float*)d_in[11];
  const float* vb1    = (const float*)d_in[12];
  const float* vW2    = (const float*)d_in[13];
  const float* vb2    = (const float*)d_in[14];
  const float* vscale = (const float*)d_in[15];
  const float* cW0    = (const float*)d_in[16];
  const float* cb0    = (const float*)d_in[17];
  const float* cW1    = (const float*)d_in[18];
  const float* cb1    = (const float*)d_in[19];
  const float* cW2    = (const float*)d_in[20];
  const float* cb2    = (const float*)d_in[21];
  const float* cscale = (const float*)d_in[22];
  const float* roW    = (const float*)d_in[23];
  const float* rob    = (const float*)d_in[24];

  cudaFuncSetAttribute(sde_kernel, cudaFuncAttributeMaxDynamicSharedMemorySize,
                       (int)sizeof(Smem));

  transpose_kernel<<<148, 256>>>(cW2, vW2);
  sde_kernel<<<NCTA, NTHR, sizeof(Smem)>>>(
      ts, z0, dW, iW0, ib0, iW1, ib1, iW2, ib2,
      vW0, vb0, vW1, vb1, vb2, vscale,
      cW0, cb0, cW1, cb1, cb2, cscale, roW, rob,
      (float*)d_out);
}